// round 9
// baseline (speedup 1.0000x reference)
#include <cuda_runtime.h>
#include <cstdint>

#define SGX 32
#define SGY 24
#define SGT 5
#define NBINS (2 * SGT * SGY * SGX)   // 7680

#define BLOCKS   296
#define THREADS1 1024
#define THREADS2 1024

#define TQ_MAXI  2097151u
#define TQ_SCALE (2097151.0f / 50.0f)     // t in [0,50] -> [0, 2^21-1]
#define C_FIXED  (5.0f / 2097152.0f)      // fixed thresholds at k*2^21/5
#define WGUARD   1024u
#define FIVE_W   (5u * WGUARD)            // 5120 (u = 5*tq domain)
#define BUF_CAP  (4u * 1024u * 1024u)     // 16 MB side buffer (exp. use ~100k)

__device__ uint32_t     g_buf[BUF_CAP];
__device__ unsigned int g_counts[NBINS];     // fixed-threshold histogram (+fixup)
__device__ unsigned int g_counts2[NBINS];    // slow-path histogram
__device__ unsigned int g_bqmin[BLOCKS];
__device__ unsigned int g_bqmax[BLOCKS];
__device__ unsigned int g_bufcnt;            // zero-init; reset by pass2 finalizer
__device__ unsigned int g_done;              // ditto

// decode one event -> quantized t, fixed-threshold bin, packed record
__device__ __forceinline__ void proc_event(float4 e, unsigned int& tq,
                                           int& bin, uint32_t& rec) {
    int xv = (int)(e.x * 0.05f);             // 32/640
    int yv = (int)(e.y * 0.05f);             // 24/480
    xv = min(max(xv, 0), SGX - 1);
    yv = min(max(yv, 0), SGY - 1);
    float tf = fmaxf(fmaf(e.z, TQ_SCALE, 0.5f), 0.0f);
    tq = min((unsigned int)tf, TQ_MAXI);
    unsigned int p = (e.w > 0.0f) ? 0u : 1u;
    int sp = (int)(p * 3840u) + yv * SGX + xv;        // spatial+polarity base
    int tv = (int)((float)tq * C_FIXED);              // 0..4 (tq < 2^21)
    bin = tv * 768 + sp;
    rec = (((p << 10) | ((unsigned int)yv << 5) | (unsigned int)xv) << 21) | tq;
}

// warp-aggregated append of near-boundary events
__device__ __forceinline__ void buf_append(bool pred, uint32_t rec) {
    unsigned int mask = __ballot_sync(__activemask(), pred);
    if (!pred) return;
    int leader = __ffs(mask) - 1;
    int lane   = threadIdx.x & 31;
    unsigned int base = 0;
    if (lane == leader) base = atomicAdd(&g_bufcnt, (unsigned int)__popc(mask));
    base = __shfl_sync(mask, base, leader);
    unsigned int idx = base + (unsigned int)__popc(mask & ((1u << lane) - 1u));
    if (idx < BUF_CAP) g_buf[idx] = rec;
}

// ---------------------------------------------------------------------------
// Pass 1: single stream over events. Speculative fixed-threshold smem
// histogram + qmin/qmax partials + side buffer of near-boundary events.
// ---------------------------------------------------------------------------
__global__ __launch_bounds__(THREADS1, 2)
void pass1_kernel(const float4* __restrict__ ev, int n) {
    __shared__ unsigned int sh[NBINS];
    for (int b = threadIdx.x; b < NBINS; b += blockDim.x) sh[b] = 0u;
    __syncthreads();

    unsigned int tqmin = 0xFFFFFFFFu;
    unsigned int tqmax = 0u;
    int stride = gridDim.x * blockDim.x;
    int i = blockIdx.x * blockDim.x + threadIdx.x;

    for (; i + stride < n; i += 2 * stride) {
        float4 e0 = __ldcs(ev + i);
        float4 e1 = __ldcs(ev + i + stride);
        unsigned int t0, t1; int b0, b1i; uint32_t r0, r1;
        proc_event(e0, t0, b0, r0);
        proc_event(e1, t1, b1i, r1);
        atomicAdd(&sh[b0], 1u);
        atomicAdd(&sh[b1i], 1u);
        tqmin = min(tqmin, min(t0, t1));
        tqmax = max(tqmax, max(t0, t1));
        unsigned int u0 = t0 * 5u, u1 = t1 * 5u;
        bool w0 = ((u0 + FIVE_W) & 0x1FFFFFu) < 2u * FIVE_W;
        bool w1 = ((u1 + FIVE_W) & 0x1FFFFFu) < 2u * FIVE_W;
        buf_append(w0, r0);
        buf_append(w1, r1);
    }
    #pragma unroll 1
    for (; i < n; i += stride) {
        float4 e = __ldcs(ev + i);
        unsigned int t; int b; uint32_t r;
        proc_event(e, t, b, r);
        atomicAdd(&sh[b], 1u);
        tqmin = min(tqmin, t);
        tqmax = max(tqmax, t);
        unsigned int u = t * 5u;
        buf_append(((u + FIVE_W) & 0x1FFFFFu) < 2u * FIVE_W, r);
    }

    // block minmax reduce -> per-block partials
    #pragma unroll
    for (int o = 16; o > 0; o >>= 1) {
        tqmin = min(tqmin, __shfl_xor_sync(0xFFFFFFFFu, tqmin, o));
        tqmax = max(tqmax, __shfl_xor_sync(0xFFFFFFFFu, tqmax, o));
    }
    __shared__ unsigned int smin[32], smax[32];
    int wid = threadIdx.x >> 5;
    int lid = threadIdx.x & 31;
    if (lid == 0) { smin[wid] = tqmin; smax[wid] = tqmax; }
    __syncthreads();
    if (wid == 0) {
        int nw = blockDim.x >> 5;
        tqmin = (lid < nw) ? smin[lid] : 0xFFFFFFFFu;
        tqmax = (lid < nw) ? smax[lid] : 0u;
        #pragma unroll
        for (int o = 16; o > 0; o >>= 1) {
            tqmin = min(tqmin, __shfl_xor_sync(0xFFFFFFFFu, tqmin, o));
            tqmax = max(tqmax, __shfl_xor_sync(0xFFFFFFFFu, tqmax, o));
        }
        if (lid == 0) {
            g_bqmin[blockIdx.x] = tqmin;
            g_bqmax[blockIdx.x] = tqmax;
        }
    }

    // flush speculative histogram
    for (int b = threadIdx.x; b < NBINS; b += blockDim.x) {
        unsigned int v = sh[b];
        if (v) atomicAdd(&g_counts[b], v);
    }
}

// ---------------------------------------------------------------------------
// Pass 2: exact thresholds; fast path = fixup buffered events; slow path =
// full re-histogram from events. Last block finalizes + resets all state.
// ---------------------------------------------------------------------------
__global__ __launch_bounds__(THREADS2, 2)
void pass2_kernel(const float4* __restrict__ ev, int n,
                  float* __restrict__ out, float inv_s) {
    __shared__ unsigned int sh[NBINS];
    __shared__ unsigned int wmin[32], wmax[32];
    __shared__ unsigned int s_qmin, s_qmax, s_b[5];
    __shared__ int s_fast, s_degen;
    __shared__ bool s_last;

    // reduce per-block partials
    unsigned int tqmin = 0xFFFFFFFFu, tqmax = 0u;
    for (int b = threadIdx.x; b < BLOCKS; b += blockDim.x) {
        tqmin = min(tqmin, g_bqmin[b]);
        tqmax = max(tqmax, g_bqmax[b]);
    }
    #pragma unroll
    for (int o = 16; o > 0; o >>= 1) {
        tqmin = min(tqmin, __shfl_xor_sync(0xFFFFFFFFu, tqmin, o));
        tqmax = max(tqmax, __shfl_xor_sync(0xFFFFFFFFu, tqmax, o));
    }
    int wid = threadIdx.x >> 5;
    int lid = threadIdx.x & 31;
    if (lid == 0) { wmin[wid] = tqmin; wmax[wid] = tqmax; }
    __syncthreads();
    if (threadIdx.x == 0) {
        int nw = blockDim.x >> 5;
        unsigned int m0 = wmin[0], m1 = wmax[0];
        for (int w = 1; w < nw; w++) { m0 = min(m0, wmin[w]); m1 = max(m1, wmax[w]); }
        s_qmin = m0; s_qmax = m1;
        int fast = 0, degen = 0;
        if (m1 > m0) {
            fast = 1;
            unsigned long long range = (unsigned long long)(m1 - m0);
            for (unsigned long long k = 1; k <= 4; k++) {
                unsigned long long bk = (unsigned long long)m0 + (k * range + 4ull) / 5ull;
                long long dev = (long long)(5ull * bk) - (long long)(k * 2097152ull);
                if (dev < -4000ll || dev > 4000ll) fast = 0;
                s_b[k] = (unsigned int)bk;
            }
        } else {
            degen = 1;
        }
        if (g_bufcnt > BUF_CAP) fast = 0;
        s_fast = fast; s_degen = degen;
    }
    __syncthreads();

    int stride = gridDim.x * blockDim.x;

    if (s_fast) {
        // ---- fast path: fixup the buffered near-boundary events ----
        unsigned int b1 = s_b[1], b2 = s_b[2], b3 = s_b[3], b4 = s_b[4];
        int cnt = (int)min(g_bufcnt, BUF_CAP);
        for (int j = blockIdx.x * blockDim.x + threadIdx.x; j < cnt; j += stride) {
            uint32_t r = g_buf[j];
            unsigned int tq = r & 0x1FFFFFu;
            int tv_f = (int)((float)tq * C_FIXED);           // identical expr to pass1
            int tv_e = (int)(tq >= b1) + (int)(tq >= b2)
                     + (int)(tq >= b3) + (int)(tq >= b4);
            if (tv_e != tv_f) {
                unsigned int s  = r >> 21;
                int sp = (int)((s >> 10) * 3840u) + (int)(s & 1023u);
                atomicSub(&g_counts[tv_f * 768 + sp], 1u);
                atomicAdd(&g_counts[tv_e * 768 + sp], 1u);
            }
        }
    } else {
        // ---- slow path: exact re-histogram from the original events ----
        for (int b = threadIdx.x; b < NBINS; b += blockDim.x) sh[b] = 0u;
        __syncthreads();
        unsigned int qmin = s_qmin;
        float sc = s_degen ? (0.1f * (50.0f / 2097151.0f))
                           : (5.0f / (float)(s_qmax - s_qmin));
        unsigned int off = s_degen ? 0u : qmin;
        for (int i = blockIdx.x * blockDim.x + threadIdx.x; i < n; i += stride) {
            float4 e = __ldcs(ev + i);
            unsigned int tq; int bf; uint32_t r;
            proc_event(e, tq, bf, r);
            int tv = (int)((float)(tq - min(tq, off) + (tq >= off ? 0u : 0u)
                            ) * 0.0f);  // placeholder avoided below
            // recompute cleanly:
            float tn = (float)(tq - (tq > off ? off : tq < off ? tq : off)) ;
            (void)tn; (void)tv;
            unsigned int d = (tq > off) ? (tq - off) : 0u;
            int tvv = (int)((float)d * sc);
            tvv = min(max(tvv, 0), SGT - 1);
            unsigned int s = r >> 21;
            int sp = (int)((s >> 10) * 3840u) + (int)(s & 1023u);
            atomicAdd(&sh[tvv * 768 + sp], 1u);
        }
        __syncthreads();
        for (int b = threadIdx.x; b < NBINS; b += blockDim.x) {
            unsigned int v = sh[b];
            if (v) atomicAdd(&g_counts2[b], v);
        }
    }

    // ---- last-block finalize + full state reset for graph replay ----
    __threadfence();
    __syncthreads();
    if (threadIdx.x == 0) {
        unsigned int t = atomicAdd(&g_done, 1u);
        s_last = (t == gridDim.x - 1);
    }
    __syncthreads();
    if (s_last) {
        __threadfence();
        int fast = s_fast;
        for (int b = threadIdx.x; b < NBINS; b += blockDim.x) {
            unsigned int c = fast ? g_counts[b] : g_counts2[b];
            out[b] = (float)c * inv_s;
            g_counts[b]  = 0u;
            g_counts2[b] = 0u;
        }
        if (threadIdx.x == 0) {
            g_bufcnt = 0u;
            g_done   = 0u;
            __threadfence();
        }
    }
}

extern "C" void kernel_launch(void* const* d_in, const int* in_sizes, int n_in,
                              void* d_out, int out_size) {
    const float4* ev = (const float4*)d_in[0];
    int n = in_sizes[0] / 4;              // events: (N, 4) f32, N = 2^24
    float* out = (float*)d_out;

    // every event lands in exactly one bin -> grid.sum() == N exactly
    float inv_s = (n > 0) ? (1.0f / (float)n) : 1.0f;

    pass1_kernel<<<BLOCKS, THREADS1>>>(ev, n);
    pass2_kernel<<<BLOCKS, THREADS2>>>(ev, n, out, inv_s);
}

// round 10
// speedup vs baseline: 1.2972x; 1.2972x over previous
#include <cuda_runtime.h>
#include <cstdint>

#define SGX 32
#define SGY 24
#define SGT 5
#define NBINS (2 * SGT * SGY * SGX)   // 7680

#define BLOCKS1  444                  // pass1: 148 x 3
#define THREADS1 512
#define BLOCKS2  296
#define THREADS2 1024
#define NPART    BLOCKS1

#define N_MAX    16777216
#define TQ_MAXI  2097151u
#define TQ_SCALE (2097151.0f / 50.0f)     // t in [0,50] -> [0, 2^21-1]
#define C_FIXED  (5.0f / 2097152.0f)      // exact: 5 * 2^-21
#define GUARD_U  1280u                    // guard band in u = 5*tq units
#define CHECK_DEV 1000ll                  // |5*bk - k*2^21| must be <= this < GUARD_U
#define BUF_CAP  (1u << 20)               // 4 MB side buffer (expected ~20k entries)

__device__ uint32_t     g_pack[N_MAX / 2 + 1];   // 2 x u16 bins per word (32 MB)
__device__ uint32_t     g_buf[BUF_CAP];          // near-boundary packed records
__device__ unsigned int g_counts[NBINS];         // fast-path histogram
__device__ unsigned int g_counts2[NBINS];        // slow-path histogram
__device__ unsigned int g_bqmin[NPART];
__device__ unsigned int g_bqmax[NPART];
__device__ unsigned int g_bufcnt;                // reset by finalizer (bss-zero initially)
__device__ unsigned int g_done;

// decode event -> quantized t, u16 bin code (sentinel if near boundary), record
__device__ __forceinline__ void decode(float4 e, unsigned int& tq,
                                       unsigned int& code, uint32_t& rec, bool& bdry) {
    int xv = min(max((int)(e.x * 0.05f), 0), SGX - 1);
    int yv = min(max((int)(e.y * 0.05f), 0), SGY - 1);
    float tf = fmaxf(fmaf(e.z, TQ_SCALE, 0.5f), 0.0f);
    tq = min((unsigned int)tf, TQ_MAXI);
    unsigned int p = (e.w > 0.0f) ? 0u : 1u;
    unsigned int sp = p * 3840u + (unsigned int)yv * 32u + (unsigned int)xv;
    unsigned int u = tq * 5u;
    bdry = ((u + GUARD_U) & 0x1FFFFFu) < 2u * GUARD_U;   // within W of a fixed point
    int tv = (int)((float)tq * C_FIXED);                 // exact floor(5*tq/2^21)
    code = bdry ? 0xFFFFu : ((unsigned int)tv * 768u + sp);
    rec = (((p << 10) | ((unsigned int)yv << 5) | (unsigned int)xv) << 21) | tq;
}

// warp-aggregated side-buffer append (pred is rare)
__device__ __forceinline__ void buf_append(bool pred, uint32_t rec) {
    unsigned int mask = __ballot_sync(__activemask(), pred);
    if (!pred) return;
    int leader = __ffs(mask) - 1;
    int lane   = threadIdx.x & 31;
    unsigned int base = 0;
    if (lane == leader) base = atomicAdd(&g_bufcnt, (unsigned int)__popc(mask));
    base = __shfl_sync(mask, base, leader);
    unsigned int idx = base + (unsigned int)__popc(mask & ((1u << lane) - 1u));
    if (idx < BUF_CAP) g_buf[idx] = rec;
}

// ---------------------------------------------------------------------------
// Pass 1: stream events (evict-first), emit u16 speculative bins (packed 2/word),
// qmin/qmax partials, near-boundary side buffer. NO histogram atomics here.
// ---------------------------------------------------------------------------
__global__ __launch_bounds__(THREADS1, 3)
void pass1_kernel(const float4* __restrict__ ev, int n) {
    int gtid = blockIdx.x * blockDim.x + threadIdx.x;
    int stride = gridDim.x * blockDim.x;
    for (int b = gtid; b < NBINS; b += stride) { g_counts[b] = 0u; g_counts2[b] = 0u; }
    if (gtid == 0) g_done = 0u;

    unsigned int tqmin = 0xFFFFFFFFu;
    unsigned int tqmax = 0u;
    int npair = n >> 1;
    int p = gtid;

    for (; p + stride < npair; p += 2 * stride) {
        float4 e0 = __ldcs(ev + 2 * p);
        float4 e1 = __ldcs(ev + 2 * p + 1);
        float4 e2 = __ldcs(ev + 2 * (p + stride));
        float4 e3 = __ldcs(ev + 2 * (p + stride) + 1);
        unsigned int t0, t1, t2, t3, c0, c1, c2, c3;
        uint32_t r0, r1, r2, r3;
        bool w0, w1, w2, w3;
        decode(e0, t0, c0, r0, w0);
        decode(e1, t1, c1, r1, w1);
        decode(e2, t2, c2, r2, w2);
        decode(e3, t3, c3, r3, w3);
        g_pack[p]          = c0 | (c1 << 16);
        g_pack[p + stride] = c2 | (c3 << 16);
        tqmin = min(tqmin, min(min(t0, t1), min(t2, t3)));
        tqmax = max(tqmax, max(max(t0, t1), max(t2, t3)));
        buf_append(w0, r0);
        buf_append(w1, r1);
        buf_append(w2, r2);
        buf_append(w3, r3);
    }
    #pragma unroll 1
    for (; p < npair; p += stride) {
        float4 e0 = __ldcs(ev + 2 * p);
        float4 e1 = __ldcs(ev + 2 * p + 1);
        unsigned int t0, t1, c0, c1;
        uint32_t r0, r1;
        bool w0, w1;
        decode(e0, t0, c0, r0, w0);
        decode(e1, t1, c1, r1, w1);
        g_pack[p] = c0 | (c1 << 16);
        tqmin = min(tqmin, min(t0, t1));
        tqmax = max(tqmax, max(t0, t1));
        buf_append(w0, r0);
        buf_append(w1, r1);
    }
    // odd-count tail event
    if (gtid == 0 && (n & 1)) {
        float4 e = __ldcs(ev + (n - 1));
        unsigned int t, c; uint32_t r; bool w;
        decode(e, t, c, r, w);
        reinterpret_cast<unsigned short*>(g_pack)[n - 1] = (unsigned short)c;
        tqmin = min(tqmin, t);
        tqmax = max(tqmax, t);
        buf_append(w, r);
    }

    // block minmax reduce -> per-block partials
    #pragma unroll
    for (int o = 16; o > 0; o >>= 1) {
        tqmin = min(tqmin, __shfl_xor_sync(0xFFFFFFFFu, tqmin, o));
        tqmax = max(tqmax, __shfl_xor_sync(0xFFFFFFFFu, tqmax, o));
    }
    __shared__ unsigned int smin[16], smax[16];
    int wid = threadIdx.x >> 5;
    int lid = threadIdx.x & 31;
    if (lid == 0) { smin[wid] = tqmin; smax[wid] = tqmax; }
    __syncthreads();
    if (wid == 0) {
        int nw = blockDim.x >> 5;
        tqmin = (lid < nw) ? smin[lid] : 0xFFFFFFFFu;
        tqmax = (lid < nw) ? smax[lid] : 0u;
        #pragma unroll
        for (int o = 8; o > 0; o >>= 1) {
            tqmin = min(tqmin, __shfl_xor_sync(0xFFFFFFFFu, tqmin, o));
            tqmax = max(tqmax, __shfl_xor_sync(0xFFFFFFFFu, tqmax, o));
        }
        if (lid == 0) {
            g_bqmin[blockIdx.x] = tqmin;
            g_bqmax[blockIdx.x] = tqmax;
        }
    }
}

// ---------------------------------------------------------------------------
// Pass 2: verify thresholds; fast path = histogram u16 bins + fixup buffer;
// slow path = exact re-histogram from events. Finalize + reset state.
// ---------------------------------------------------------------------------
__global__ __launch_bounds__(THREADS2, 2)
void pass2_kernel(const float4* __restrict__ ev, int n,
                  float* __restrict__ out, float inv_s) {
    __shared__ unsigned int sh[NBINS];
    __shared__ unsigned int wmin[32], wmax[32];
    __shared__ unsigned int s_b[5];
    __shared__ int s_fast;
    __shared__ unsigned int s_bufcnt;
    __shared__ bool s_last;

    for (int b = threadIdx.x; b < NBINS; b += blockDim.x) sh[b] = 0u;

    // reduce per-block partials
    unsigned int tqmin = 0xFFFFFFFFu, tqmax = 0u;
    for (int b = threadIdx.x; b < NPART; b += blockDim.x) {
        tqmin = min(tqmin, g_bqmin[b]);
        tqmax = max(tqmax, g_bqmax[b]);
    }
    #pragma unroll
    for (int o = 16; o > 0; o >>= 1) {
        tqmin = min(tqmin, __shfl_xor_sync(0xFFFFFFFFu, tqmin, o));
        tqmax = max(tqmax, __shfl_xor_sync(0xFFFFFFFFu, tqmax, o));
    }
    int wid = threadIdx.x >> 5;
    int lid = threadIdx.x & 31;
    if (lid == 0) { wmin[wid] = tqmin; wmax[wid] = tqmax; }
    __syncthreads();
    if (threadIdx.x == 0) {
        int nw = blockDim.x >> 5;
        unsigned int m0 = wmin[0], m1 = wmax[0];
        for (int w = 1; w < nw; w++) { m0 = min(m0, wmin[w]); m1 = max(m1, wmax[w]); }
        int fast = 1;
        if (m1 > m0) {
            unsigned long long range = (unsigned long long)(m1 - m0);
            for (unsigned long long k = 1; k <= 4; k++) {
                unsigned long long bk = (unsigned long long)m0 + (k * range + 4ull) / 5ull;
                long long dev = (long long)(5ull * bk) - (long long)(k * 2097152ull);
                if (dev < -CHECK_DEV || dev > CHECK_DEV) fast = 0;
                s_b[k] = (unsigned int)bk;
            }
        } else {
            // degenerate: raw-t thresholds at k*10*TQ_SCALE (ceil); dev ~= +3
            s_b[1] = 419431u;  s_b[2] = 838861u;
            s_b[3] = 1258291u; s_b[4] = 1677721u;
        }
        unsigned int bc = g_bufcnt;
        if (bc > BUF_CAP) fast = 0;
        s_bufcnt = min(bc, BUF_CAP);
        s_fast = fast;
    }
    __syncthreads();

    int stride = gridDim.x * blockDim.x;
    unsigned int b1 = s_b[1], b2 = s_b[2], b3 = s_b[3], b4 = s_b[4];

    if (s_fast) {
        // ---- main loop: u16 speculative bins (32 MB, L2-hot) ----
        const uint4* pk4 = reinterpret_cast<const uint4*>(g_pack);
        int npair = n >> 1;
        int nw4 = npair >> 2;      // uint4 words (8 events each)
        int i = blockIdx.x * blockDim.x + threadIdx.x;
        for (; i + stride < nw4; i += 2 * stride) {
            uint4 a = pk4[i];
            uint4 b = pk4[i + stride];
            #pragma unroll
            for (int q = 0; q < 4; q++) {
                unsigned int w = (&a.x)[q];
                unsigned int v0 = w & 0xFFFFu, v1 = w >> 16;
                if (v0 != 0xFFFFu) atomicAdd(&sh[v0], 1u);
                if (v1 != 0xFFFFu) atomicAdd(&sh[v1], 1u);
            }
            #pragma unroll
            for (int q = 0; q < 4; q++) {
                unsigned int w = (&b.x)[q];
                unsigned int v0 = w & 0xFFFFu, v1 = w >> 16;
                if (v0 != 0xFFFFu) atomicAdd(&sh[v0], 1u);
                if (v1 != 0xFFFFu) atomicAdd(&sh[v1], 1u);
            }
        }
        #pragma unroll 1
        for (; i < nw4; i += stride) {
            uint4 a = pk4[i];
            #pragma unroll
            for (int q = 0; q < 4; q++) {
                unsigned int w = (&a.x)[q];
                unsigned int v0 = w & 0xFFFFu, v1 = w >> 16;
                if (v0 != 0xFFFFu) atomicAdd(&sh[v0], 1u);
                if (v1 != 0xFFFFu) atomicAdd(&sh[v1], 1u);
            }
        }
        // tail u16s beyond nw4*8 events
        #pragma unroll 1
        for (int j = (nw4 << 3) + blockIdx.x * blockDim.x + threadIdx.x; j < n; j += stride) {
            unsigned int v = reinterpret_cast<const unsigned short*>(g_pack)[j];
            if (v != 0xFFFFu) atomicAdd(&sh[v], 1u);
        }

        __syncthreads();
        for (int b = threadIdx.x; b < NBINS; b += blockDim.x) {
            unsigned int v = sh[b];
            if (v) atomicAdd(&g_counts[b], v);
        }

        // ---- fixup: buffered near-boundary events, exact thresholds ----
        int cnt = (int)s_bufcnt;
        for (int j = blockIdx.x * blockDim.x + threadIdx.x; j < cnt; j += stride) {
            uint32_t r = g_buf[j];
            unsigned int tq = r & 0x1FFFFFu;
            int tv = (int)(tq >= b1) + (int)(tq >= b2) + (int)(tq >= b3) + (int)(tq >= b4);
            unsigned int s = r >> 21;
            int sp = (int)((s >> 10) * 3840u) + (int)(s & 1023u);
            atomicAdd(&g_counts[tv * 768 + sp], 1u);
        }
    } else {
        // ---- slow path: exact re-histogram from original events ----
        for (int i = blockIdx.x * blockDim.x + threadIdx.x; i < n; i += stride) {
            float4 e = __ldcs(ev + i);
            unsigned int tq, c; uint32_t r; bool w;
            decode(e, tq, c, r, w);
            int tv = (int)(tq >= b1) + (int)(tq >= b2) + (int)(tq >= b3) + (int)(tq >= b4);
            unsigned int s = r >> 21;
            int sp = (int)((s >> 10) * 3840u) + (int)(s & 1023u);
            atomicAdd(&sh[tv * 768 + sp], 1u);
        }
        __syncthreads();
        for (int b = threadIdx.x; b < NBINS; b += blockDim.x) {
            unsigned int v = sh[b];
            if (v) atomicAdd(&g_counts2[b], v);
        }
    }

    // ---- last-block finalize + state reset for graph replay ----
    __threadfence();
    __syncthreads();
    if (threadIdx.x == 0) {
        unsigned int t = atomicAdd(&g_done, 1u);
        s_last = (t == gridDim.x - 1);
    }
    __syncthreads();
    if (s_last) {
        __threadfence();
        int fast = s_fast;
        for (int b = threadIdx.x; b < NBINS; b += blockDim.x) {
            unsigned int c = fast ? g_counts[b] : g_counts2[b];
            out[b] = (float)c * inv_s;
            g_counts[b]  = 0u;
            g_counts2[b] = 0u;
        }
        if (threadIdx.x == 0) {
            g_bufcnt = 0u;
            g_done   = 0u;
            __threadfence();
        }
    }
}

extern "C" void kernel_launch(void* const* d_in, const int* in_sizes, int n_in,
                              void* d_out, int out_size) {
    const float4* ev = (const float4*)d_in[0];
    int n = in_sizes[0] / 4;              // events: (N, 4) f32, N = 2^24
    float* out = (float*)d_out;

    // every event lands in exactly one bin -> grid.sum() == N exactly
    float inv_s = (n > 0) ? (1.0f / (float)n) : 1.0f;

    pass1_kernel<<<BLOCKS1, THREADS1>>>(ev, n);
    pass2_kernel<<<BLOCKS2, THREADS2>>>(ev, n, out, inv_s);
}

// round 11
// speedup vs baseline: 1.3478x; 1.0390x over previous
#include <cuda_runtime.h>
#include <cstdint>

#define SGX 32
#define SGY 24
#define SGT 5
#define NBINS (2 * SGT * SGY * SGX)   // 7680

#define BLOCKS   296
#define THREADS1 1024                 // pass1: 2 CTAs x 1024 = 100% occ/SM
#define THREADS2 1024                 // pass2: 2 CTAs x 1024 = 100% occ/SM

#define N_MAX    16777216
#define TQ_MAX   2097151.0f           // 2^21 - 1
#define TQ_SCALE (TQ_MAX / 50.0f)     // t in [0,50] -> [0, 2^21-1]

__device__ uint32_t g_rec[N_MAX];     // 64 MB packed records
__device__ unsigned int g_counts[NBINS];
__device__ unsigned int g_bqmin[BLOCKS];
__device__ unsigned int g_bqmax[BLOCKS];
__device__ unsigned int g_done;

// rec = (s << 21) | tq, s = p<<10 | yv<<5 | xv
__device__ __forceinline__ uint32_t pack_event(float4 e, unsigned int& tq) {
    int xv = (int)(e.x * 0.05f);             // 32/640
    int yv = (int)(e.y * 0.05f);             // 24/480
    xv = min(max(xv, 0), SGX - 1);
    yv = min(max(yv, 0), SGY - 1);
    tq = (unsigned int)fmaf(e.z, TQ_SCALE, 0.5f);   // monotone round-to-nearest
    unsigned int pbit = (e.w > 0.0f) ? 0u : 1u;
    unsigned int s = (pbit << 10) | ((unsigned int)yv << 5) | (unsigned int)xv;
    return (s << 21) | tq;
}

// ---------------------------------------------------------------------------
// Pass 1: stream events (evict-first), pack records, per-block qmin/qmax,
// zero accumulator + done flag.  Full occupancy, 2-way unroll (regs <= 32).
// ---------------------------------------------------------------------------
__global__ __launch_bounds__(THREADS1, 2)
void pass1_kernel(const float4* __restrict__ ev, int n) {
    int gtid = blockIdx.x * blockDim.x + threadIdx.x;
    int stride = gridDim.x * blockDim.x;
    for (int b = gtid; b < NBINS; b += stride) g_counts[b] = 0u;
    if (gtid == 0) g_done = 0u;

    unsigned int tqmin = 0xFFFFFFFFu;
    unsigned int tqmax = 0u;
    int i = gtid;

    for (; i + stride < n; i += 2 * stride) {
        float4 e0 = __ldcs(ev + i);
        float4 e1 = __ldcs(ev + i + stride);
        unsigned int t0, t1;
        uint32_t r0 = pack_event(e0, t0);
        uint32_t r1 = pack_event(e1, t1);
        g_rec[i]          = r0;
        g_rec[i + stride] = r1;
        tqmin = min(tqmin, min(t0, t1));
        tqmax = max(tqmax, max(t0, t1));
    }
    #pragma unroll 1
    for (; i < n; i += stride) {
        float4 e = __ldcs(ev + i);
        unsigned int t;
        g_rec[i] = pack_event(e, t);
        tqmin = min(tqmin, t);
        tqmax = max(tqmax, t);
    }

    // warp reduce
    #pragma unroll
    for (int o = 16; o > 0; o >>= 1) {
        tqmin = min(tqmin, __shfl_xor_sync(0xFFFFFFFFu, tqmin, o));
        tqmax = max(tqmax, __shfl_xor_sync(0xFFFFFFFFu, tqmax, o));
    }
    __shared__ unsigned int smin[32], smax[32];
    int wid = threadIdx.x >> 5;
    int lid = threadIdx.x & 31;
    if (lid == 0) { smin[wid] = tqmin; smax[wid] = tqmax; }
    __syncthreads();
    if (wid == 0) {
        int nw = blockDim.x >> 5;
        tqmin = (lid < nw) ? smin[lid] : 0xFFFFFFFFu;
        tqmax = (lid < nw) ? smax[lid] : 0u;
        #pragma unroll
        for (int o = 16; o > 0; o >>= 1) {
            tqmin = min(tqmin, __shfl_xor_sync(0xFFFFFFFFu, tqmin, o));
            tqmax = max(tqmax, __shfl_xor_sync(0xFFFFFFFFu, tqmax, o));
        }
        if (lid == 0) {
            g_bqmin[blockIdx.x] = tqmin;
            g_bqmax[blockIdx.x] = tqmax;
        }
    }
}

// ---------------------------------------------------------------------------
// Pass 2: reduce partials, histogram L2-hot records (float decode),
// flush, last-block finalize.  (exact R8 configuration: 22.7us)
// ---------------------------------------------------------------------------
__device__ __forceinline__ int bin_of_rec(uint32_t r, unsigned int toff, float sc) {
    unsigned int tq = r & 0x1FFFFFu;
    unsigned int s  = r >> 21;
    int tv = (int)((float)(tq - toff) * sc);     // toff <= tq always (global min)
    tv = min(max(tv, 0), SGT - 1);
    unsigned int rest = s & 1023u;               // yv*32 + xv
    unsigned int p    = s >> 10;
    return tv * 768 + (int)rest + (int)(p * 3840u);
}

__global__ __launch_bounds__(THREADS2, 2)
void pass2_kernel(int n, float* __restrict__ out, float inv_s) {
    __shared__ unsigned int sh[NBINS];
    for (int i = threadIdx.x; i < NBINS; i += blockDim.x) sh[i] = 0u;

    // reduce the per-block partials
    unsigned int tqmin = 0xFFFFFFFFu, tqmax = 0u;
    for (int b = threadIdx.x; b < BLOCKS; b += blockDim.x) {
        tqmin = min(tqmin, g_bqmin[b]);
        tqmax = max(tqmax, g_bqmax[b]);
    }
    #pragma unroll
    for (int o = 16; o > 0; o >>= 1) {
        tqmin = min(tqmin, __shfl_xor_sync(0xFFFFFFFFu, tqmin, o));
        tqmax = max(tqmax, __shfl_xor_sync(0xFFFFFFFFu, tqmax, o));
    }
    __shared__ unsigned int wmin[32], wmax[32];
    __shared__ unsigned int s_toff;
    __shared__ float s_sc;
    int wid = threadIdx.x >> 5;
    int lid = threadIdx.x & 31;
    if (lid == 0) { wmin[wid] = tqmin; wmax[wid] = tqmax; }
    __syncthreads();
    if (threadIdx.x == 0) {
        int nw = blockDim.x >> 5;
        unsigned int m0 = wmin[0], m1 = wmax[0];
        for (int w = 1; w < nw; w++) { m0 = min(m0, wmin[w]); m1 = max(m1, wmax[w]); }
        if (m1 > m0) {
            s_toff = m0;
            s_sc   = 5.0f / (float)(m1 - m0);          // (tq-tqmin)/range * 5
        } else {
            s_toff = 0u;
            s_sc   = 0.1f * (50.0f / TQ_MAX);          // raw t * 0.1 (degenerate)
        }
    }
    __syncthreads();
    unsigned int toff = s_toff;
    float sc = s_sc;

    const uint4* rec4 = reinterpret_cast<const uint4*>(g_rec);
    int n4 = n >> 2;
    int stride = gridDim.x * blockDim.x;
    int i = blockIdx.x * blockDim.x + threadIdx.x;

    // 2 x uint4 (8 events) per iteration for load MLP over L2 hits
    for (; i + stride < n4; i += 2 * stride) {
        uint4 a = rec4[i];
        uint4 b = rec4[i + stride];
        atomicAdd(&sh[bin_of_rec(a.x, toff, sc)], 1u);
        atomicAdd(&sh[bin_of_rec(a.y, toff, sc)], 1u);
        atomicAdd(&sh[bin_of_rec(a.z, toff, sc)], 1u);
        atomicAdd(&sh[bin_of_rec(a.w, toff, sc)], 1u);
        atomicAdd(&sh[bin_of_rec(b.x, toff, sc)], 1u);
        atomicAdd(&sh[bin_of_rec(b.y, toff, sc)], 1u);
        atomicAdd(&sh[bin_of_rec(b.z, toff, sc)], 1u);
        atomicAdd(&sh[bin_of_rec(b.w, toff, sc)], 1u);
    }
    #pragma unroll 1
    for (; i < n4; i += stride) {
        uint4 a = rec4[i];
        atomicAdd(&sh[bin_of_rec(a.x, toff, sc)], 1u);
        atomicAdd(&sh[bin_of_rec(a.y, toff, sc)], 1u);
        atomicAdd(&sh[bin_of_rec(a.z, toff, sc)], 1u);
        atomicAdd(&sh[bin_of_rec(a.w, toff, sc)], 1u);
    }
    // scalar tail (n not multiple of 4)
    #pragma unroll 1
    for (int j = (n4 << 2) + blockIdx.x * blockDim.x + threadIdx.x; j < n; j += stride) {
        atomicAdd(&sh[bin_of_rec(g_rec[j], toff, sc)], 1u);
    }

    __syncthreads();
    for (int b = threadIdx.x; b < NBINS; b += blockDim.x) {
        unsigned int v = sh[b];
        if (v) atomicAdd(&g_counts[b], v);
    }

    // last-block finalize
    __shared__ bool s_last;
    __threadfence();
    __syncthreads();
    if (threadIdx.x == 0) {
        unsigned int t = atomicAdd(&g_done, 1u);
        s_last = (t == gridDim.x - 1);
    }
    __syncthreads();
    if (s_last) {
        __threadfence();
        for (int b = threadIdx.x; b < NBINS; b += blockDim.x)
            out[b] = (float)g_counts[b] * inv_s;
    }
}

extern "C" void kernel_launch(void* const* d_in, const int* in_sizes, int n_in,
                              void* d_out, int out_size) {
    const float4* ev = (const float4*)d_in[0];
    int n = in_sizes[0] / 4;              // events: (N, 4) f32, N = 2^24
    float* out = (float*)d_out;

    float inv_s = (n > 0) ? (1.0f / (float)n) : 1.0f;

    pass1_kernel<<<BLOCKS, THREADS1>>>(ev, n);
    pass2_kernel<<<BLOCKS, THREADS2>>>(n, out, inv_s);
}